// round 17
// baseline (speedup 1.0000x reference)
#include <cuda_runtime.h>
#include <cstdint>

// Problem shape (fixed by reference)
#define T_DIM 16384
#define B_DIM 64
#define E_DIM 4096

// Permuted scratch layout for a 512-thread scan (32 elements/thread):
//   PERM(t) = (t & 31) * 512 + (t >> 5)
// Scan thread tid owns t = 32*tid + i (i=0..31) -> addr i*512 + tid
// -> every warp access in the scan is one coalesced transaction.
__device__ __forceinline__ int PERM(int t) { return ((t & 31) << 9) | (t >> 5); }

// Scratch (allocation-free). Packed float2: (.x=alpha/A, .y=beta/B)
__device__ float2 g_ab[T_DIM];
__device__ float2 g_AB[T_DIM];
__device__ int    g_done;   // monotone across replays; exactly 512 adds/launch

// ---------------------------------------------------------------------------
// Kernel 1: gather + reduce, with the SCAN fused into the last-finishing
// block (removes the separate scan kernel launch from the graph).
// Gather shape unchanged from the verified floor config (R8/R14/R16):
// 2 rows/warp, 512-thread blocks, 512 blocks.
// Compose (ordered): compose(earlier=(A,B), later=(a,b)) = (a*A, a*B + b)
// ---------------------------------------------------------------------------
#define K1_ROWS 2
__global__ void __launch_bounds__(512) gather_scan_kernel(
        const int* __restrict__ indices, const float* __restrict__ params) {
    __shared__ int  s_last;
    __shared__ float2 sW[16];   // per-warp inclusive totals (scan phase)

    const int tid  = threadIdx.x;
    const int lane = tid & 31;
    const int wid  = tid >> 5;

    // ---- gather + reduce (identical math to the proven K1) ---------------
    {
        int gwarp = (blockIdx.x * blockDim.x + tid) >> 5;
        int t0 = gwarp * K1_ROWS;

        const float2* p2 = (const float2*)params;

        int2 i0 = ((const int2*)(indices + (size_t)t0       * B_DIM))[lane];
        int2 i1 = ((const int2*)(indices + (size_t)(t0 + 1) * B_DIM))[lane];
        float2 a0 = __ldg(&p2[i0.x]);
        float2 b0 = __ldg(&p2[i0.y]);
        float2 a1 = __ldg(&p2[i1.x]);
        float2 b1 = __ldg(&p2[i1.y]);

        float s0a = a0.x + b0.x, s0b = a0.y + b0.y;
        float s1a = a1.x + b1.x, s1b = a1.y + b1.y;
        #pragma unroll
        for (int off = 16; off > 0; off >>= 1) {
            s0a += __shfl_xor_sync(0xFFFFFFFFu, s0a, off);
            s0b += __shfl_xor_sync(0xFFFFFFFFu, s0b, off);
            s1a += __shfl_xor_sync(0xFFFFFFFFu, s1a, off);
            s1b += __shfl_xor_sync(0xFFFFFFFFu, s1b, off);
        }
        if (lane == 0) {
            g_ab[PERM(t0)]     = make_float2(s0a, s0b);
            g_ab[PERM(t0 + 1)] = make_float2(s1a, s1b);
        }
    }
    __syncthreads();

    // ---- last-block-done detection ----------------------------------------
    if (tid == 0) {
        __threadfence();                       // make this block's g_ab visible
        int old = atomicAdd(&g_done, 1);       // monotone across graph replays
        s_last = (((old + 1) & 511) == 0);     // exactly 512 adds per launch
    }
    __syncthreads();
    if (!s_last) return;
    __threadfence();                           // acquire: see all g_ab writes

    // ---- scan of 16384 elements by this single resident block -------------
    // Pass 1: thread-local ordered aggregate over 32 elements (reload later
    // from L2 instead of caching in registers -> keeps gather-phase regs low).
    float ca = 1.0f, cb = 0.0f;
    #pragma unroll
    for (int i = 0; i < 32; i++) {
        float2 e = g_ab[i * 512 + tid];
        cb = fmaf(e.x, cb, e.y);
        ca = e.x * ca;
    }

    // warp inclusive scan: new = compose(lower=(pa,pb), mine=(wa,wb))
    float wa = ca, wb = cb;
    #pragma unroll
    for (int off = 1; off < 32; off <<= 1) {
        float pa = __shfl_up_sync(0xFFFFFFFFu, wa, off);
        float pb = __shfl_up_sync(0xFFFFFFFFu, wb, off);
        float na = (lane >= off) ? wa * pa          : wa;
        float nb = (lane >= off) ? fmaf(wa, pb, wb) : wb;
        wa = na; wb = nb;
    }
    if (lane == 31) sW[wid] = make_float2(wa, wb);
    __syncthreads();

    // warp 0 scans the 16 warp totals (lanes 0..15)
    if (wid == 0) {
        float xa = (lane < 16) ? sW[lane].x : 1.0f;
        float xb = (lane < 16) ? sW[lane].y : 0.0f;
        #pragma unroll
        for (int off = 1; off < 16; off <<= 1) {
            float pa = __shfl_up_sync(0xFFFFFFFFu, xa, off);
            float pb = __shfl_up_sync(0xFFFFFFFFu, xb, off);
            float na = (lane >= off) ? xa * pa          : xa;
            float nb = (lane >= off) ? fmaf(xa, pb, xb) : xb;
            xa = na; xb = nb;
        }
        if (lane < 16) sW[lane] = make_float2(xa, xb);
    }
    __syncthreads();

    // thread-exclusive prefix = compose(warp_prefix, lane_exclusive)
    float wpa = (wid > 0) ? sW[wid - 1].x : 1.0f;
    float wpb = (wid > 0) ? sW[wid - 1].y : 0.0f;
    float lea = __shfl_up_sync(0xFFFFFFFFu, wa, 1);
    float leb = __shfl_up_sync(0xFFFFFFFFu, wb, 1);
    if (lane == 0) { lea = 1.0f; leb = 0.0f; }
    float pa = lea * wpa;
    float pb = fmaf(lea, wpb, leb);

    // Pass 2: replay (reload from L2), write scanned values (coalesced)
    #pragma unroll
    for (int i = 0; i < 32; i++) {
        float2 e = g_ab[i * 512 + tid];
        pb = fmaf(e.x, pb, e.y);
        pa = e.x * pa;
        g_AB[i * 512 + tid] = make_float2(pa, pb);
    }
}

// ---------------------------------------------------------------------------
// Kernel 2 (was K3): output broadcast. out[t, e] = A[t]*M_prev[e] + B[t]
// Proven R8 shape: block = E-chunk (1024 floats as float4) x 16 t-rows,
// 256 threads, __stcs streaming stores (~6.9 TB/s = HBM write ceiling).
// sAB read adjusted for the 512-thread permutation:
//   PERM(t0+r) = ((t0&16) + r) * 512 + (t0>>5)   for r in [0,16)
// ---------------------------------------------------------------------------
#define K3_ROWS   16
#define K3_CHUNKS (E_DIM / (256 * 4))   // 4 column chunks of 1024 floats

__global__ void __launch_bounds__(256) broadcast_kernel(
        const float* __restrict__ M_prev, float* __restrict__ out) {
    __shared__ float2 sAB[K3_ROWS];

    const int t0   = blockIdx.y * K3_ROWS;   // multiple of 16
    const int grp  = t0 >> 5;
    const int base = t0 & 16;
    if (threadIdx.x < K3_ROWS) {
        sAB[threadIdx.x] = g_AB[(base + threadIdx.x) * 512 + grp];
    }

    const int col = blockIdx.x * 256 + threadIdx.x;   // float4 column index
    float4 m = __ldg(&((const float4*)M_prev)[col]);
    __syncthreads();

    float4* o4 = (float4*)out;
    #pragma unroll
    for (int r = 0; r < K3_ROWS; r++) {
        float a = sAB[r].x;
        float b = sAB[r].y;
        float4 v;
        v.x = fmaf(a, m.x, b);
        v.y = fmaf(a, m.y, b);
        v.z = fmaf(a, m.z, b);
        v.w = fmaf(a, m.w, b);
        __stcs(&o4[(size_t)(t0 + r) * (E_DIM / 4) + col], v);
    }
}

// ---------------------------------------------------------------------------
extern "C" void kernel_launch(void* const* d_in, const int* in_sizes, int n_in,
                              void* d_out, int out_size) {
    const int*   indices = (const int*)d_in[0];   // (T, B) int32 (JAX downcast)
    const float* M_prev  = (const float*)d_in[1]; // (E,)   f32
    const float* params  = (const float*)d_in[2]; // (N, 2) f32
    float*       out     = (float*)d_out;         // (T, E) f32

    // K1+K2 fused: 512 blocks x 512 threads; last block does the scan
    gather_scan_kernel<<<512, 512>>>(indices, params);

    // K3: (4 column chunks) x (1024 row groups)
    dim3 g3(K3_CHUNKS, T_DIM / K3_ROWS);
    broadcast_kernel<<<g3, 256>>>(M_prev, out);
}